// round 4
// baseline (speedup 1.0000x reference)
#include <cuda_runtime.h>
#include <math.h>

#define NL 24
#define D 1024
#define NH 16
#define SS 4096
#define HDIM 64
#define NHEAD_OUT 47   // 32 + 7 + 8

// -------- device scratch (allocation-free) --------
__device__ __align__(16) float g_q[D];
__device__ __align__(16) float g_x[D];        // layer input x (post prev LN2)
__device__ __align__(16) float g_xmid[D];     // LN1(x + attn_out)
__device__ __align__(16) float g_attnout[D];
__device__ __align__(16) float g_h1[D];
__device__ __align__(16) float g_ffout[D];
__device__ __align__(16) float g_scores[NH * SS];
__device__ __align__(16) float g_av_part[16 * D];  // [chunk][h*64+d] unnormalized
__device__ float g_m[NH * 16];   // per (head, chunk) max
__device__ float g_s[NH * 16];   // per (head, chunk) sum of exp

// -------- reductions --------
__device__ __forceinline__ float warpReduceSum(float v) {
#pragma unroll
    for (int o = 16; o > 0; o >>= 1) v += __shfl_down_sync(0xffffffffu, v, o);
    return v;
}
__device__ __forceinline__ float warpReduceMax(float v) {
#pragma unroll
    for (int o = 16; o > 0; o >>= 1) v = fmaxf(v, __shfl_down_sync(0xffffffffu, v, o));
    return v;
}
// nw = blockDim/32 (<=16)
__device__ __forceinline__ float blockReduceSum(float v, float* red, int nw) {
    int tid = threadIdx.x;
    v = warpReduceSum(v);
    if ((tid & 31) == 0) red[tid >> 5] = v;
    __syncthreads();
    if (tid < 32) {
        float t = (tid < nw) ? red[tid] : 0.f;
        t = warpReduceSum(t);
        if (tid == 0) red[0] = t;
    }
    __syncthreads();
    float r = red[0];
    __syncthreads();
    return r;
}
__device__ __forceinline__ float blockReduceMax(float v, float* red, int nw) {
    int tid = threadIdx.x;
    v = warpReduceMax(v);
    if ((tid & 31) == 0) red[tid >> 5] = v;
    __syncthreads();
    if (tid < 32) {
        float t = (tid < nw) ? red[tid] : -INFINITY;
        t = warpReduceMax(t);
        if (tid == 0) red[0] = t;
    }
    __syncthreads();
    float r = red[0];
    __syncthreads();
    return r;
}

// LN(a+b)*sc+bi -> xs[D]; 256-thread float4 version (final_kernel)
__device__ __forceinline__ void load_ln(const float* __restrict__ a, const float* __restrict__ b,
                                        const float* __restrict__ sc, const float* __restrict__ bi,
                                        float* xs, float* red) {
    int tid = threadIdx.x;
    float4 av = ((const float4*)a)[tid];
    float4 bv = ((const float4*)b)[tid];
    av.x += bv.x; av.y += bv.y; av.z += bv.z; av.w += bv.w;
    float sum = blockReduceSum(av.x + av.y + av.z + av.w, red, 8);
    float sq  = blockReduceSum(av.x*av.x + av.y*av.y + av.z*av.z + av.w*av.w, red, 8);
    float mean = sum * (1.f / D);
    float inv = rsqrtf(sq * (1.f / D) - mean * mean + 1e-6f);
    float4 s4 = ((const float4*)sc)[tid];
    float4 b4 = ((const float4*)bi)[tid];
    float4 o;
    o.x = (av.x - mean) * inv * s4.x + b4.x;
    o.y = (av.y - mean) * inv * s4.y + b4.y;
    o.z = (av.z - mean) * inv * s4.z + b4.z;
    o.w = (av.w - mean) * inv * s4.w + b4.w;
    ((float4*)xs)[tid] = o;
}

// LN(a+b)*sc+bi -> xs[D]; 512-thread float2 version (qkv/gemv)
__device__ __forceinline__ void load_ln2(const float* __restrict__ a, const float* __restrict__ b,
                                         const float* __restrict__ sc, const float* __restrict__ bi,
                                         float* xs, float* red) {
    int tid = threadIdx.x;
    float2 av = ((const float2*)a)[tid];
    float2 bv = ((const float2*)b)[tid];
    av.x += bv.x; av.y += bv.y;
    float sum = blockReduceSum(av.x + av.y, red, 16);
    float sq  = blockReduceSum(av.x*av.x + av.y*av.y, red, 16);
    float mean = sum * (1.f / D);
    float inv = rsqrtf(sq * (1.f / D) - mean * mean + 1e-6f);
    float2 s2 = ((const float2*)sc)[tid];
    float2 b2 = ((const float2*)bi)[tid];
    float2 o;
    o.x = (av.x - mean) * inv * s2.x + b2.x;
    o.y = (av.y - mean) * inv * s2.y + b2.y;
    ((float2*)xs)[tid] = o;
}

// GEMV core for 512 threads: 32 output cols per block, float4 weight loads,
// 64-way K split (16 rows each). Returns value for col jbase+tid on tid<32.
// pr must be float[8*64*4] shared.
__device__ __forceinline__ float gemv32_core(const float* __restrict__ W, const float* xs,
                                             int jbase, float* pr) {
    int tid = threadIdx.x;
    int jq = tid & 7, ks = tid >> 3;       // jq: float4 col group, ks: K slice
    const float4* Wp = (const float4*)W + (size_t)(ks << 4) * 256 + (jbase >> 2) + jq;
    float4 acc = make_float4(0.f, 0.f, 0.f, 0.f);
#pragma unroll
    for (int i = 0; i < 16; ++i) {
        float xv = xs[(ks << 4) + i];
        float4 w = Wp[(size_t)i * 256];
        acc.x += xv * w.x; acc.y += xv * w.y; acc.z += xv * w.z; acc.w += xv * w.w;
    }
    int base = ((jq << 6) + ks) << 2;
    pr[base] = acc.x; pr[base + 1] = acc.y; pr[base + 2] = acc.z; pr[base + 3] = acc.w;
    __syncthreads();
#pragma unroll
    for (int off = 32; off > 0; off >>= 1) {
        if (ks < off) {
            int b2 = ((jq << 6) + ks) << 2;
            int b3 = ((jq << 6) + ks + off) << 2;
            pr[b2] += pr[b3]; pr[b2 + 1] += pr[b3 + 1];
            pr[b2 + 2] += pr[b3 + 2]; pr[b2 + 3] += pr[b3 + 3];
        }
        __syncthreads();
    }
    float v = 0.f;
    if (tid < 32) v = pr[((tid >> 2) << 8) + (tid & 3)];
    return v;
}

// -------- kernel A: (optional LN2 of prev layer) + q/k/v GEMVs --------
// grid = 96 (32 per matrix), 512 threads.
__global__ void __launch_bounds__(512) qkv_kernel(
    const float* __restrict__ xin, int first,
    const float* __restrict__ ln2s, const float* __restrict__ ln2b,
    const float* __restrict__ Wq, const float* __restrict__ Wk, const float* __restrict__ Wv,
    const float* __restrict__ bq, const float* __restrict__ bk, const float* __restrict__ bv,
    float* __restrict__ newc, int l) {
    __shared__ float xs[D];
    __shared__ float red[32];
    __shared__ float pr[8 * 64 * 4];
    int tid = threadIdx.x;
    if (first) {
        ((float2*)xs)[tid] = ((const float2*)xin)[tid];
    } else {
        load_ln2(g_xmid, g_ffout, ln2s, ln2b, xs, red);
    }
    __syncthreads();
    if (blockIdx.x == 0) ((float2*)g_x)[tid] = ((float2*)xs)[tid];

    int m = blockIdx.x >> 5;                  // 0=q, 1=k, 2=v
    int jbase = (blockIdx.x & 31) << 5;
    const float* W = (m == 0) ? Wq : ((m == 1) ? Wk : Wv);
    const float* B = (m == 0) ? bq : ((m == 1) ? bk : bv);
    float v = gemv32_core(W, xs, jbase, pr);
    if (tid < 32) {
        int j = jbase + tid;
        float o = v + B[j];
        if (m == 0) g_q[j] = o;
        else {
            int plane = (m == 1) ? 1 : 0;     // plane0 = v, plane1 = k
            newc[((size_t)(l * 2 + plane) * SS + (SS - 1)) * D + j] = o;
        }
    }
}

// -------- kernel B: fused cache shift + mask + attention scores --------
// grid = 4096 (one block per seq pos), 256 threads.
__global__ void __launch_bounds__(256) scores_kernel(
    const float* __restrict__ oldc, float* __restrict__ newc, int l) {
    int s = blockIdx.x;
    int tid = threadIdx.x;
    size_t vbase = (size_t)(l * 2) * SS * D;
    size_t kbase = vbase + (size_t)SS * D;
    float4 v4, k4;
    if (s < SS - 1) {
        v4 = ((const float4*)(oldc + vbase + (size_t)(s + 1) * D))[tid];
        k4 = ((const float4*)(oldc + kbase + (size_t)(s + 1) * D))[tid];
        float* vd = newc + vbase + (size_t)s * D + (tid << 2);
        float* kd = newc + kbase + (size_t)s * D + (tid << 2);
        vd[0] = v4.x; vd[1] = v4.y; vd[2] = v4.z; vd[3] = v4.w;
        kd[0] = k4.x; kd[1] = k4.y; kd[2] = k4.z; kd[3] = k4.w;
    } else {
        const float* vs = newc + vbase + (size_t)s * D + (tid << 2);
        const float* kk = newc + kbase + (size_t)s * D + (tid << 2);
        v4 = make_float4(vs[0], vs[1], vs[2], vs[3]);
        k4 = make_float4(kk[0], kk[1], kk[2], kk[3]);
    }
    int nz = (v4.x != 0.f) || (v4.y != 0.f) || (v4.z != 0.f) || (v4.w != 0.f);
    int any = __syncthreads_or(nz);
    float4 q4 = ((const float4*)g_q)[tid];
    float p = q4.x * k4.x + q4.y * k4.y + q4.z * k4.z + q4.w * k4.w;
    p += __shfl_down_sync(0xffffffffu, p, 8, 16);
    p += __shfl_down_sync(0xffffffffu, p, 4, 16);
    p += __shfl_down_sync(0xffffffffu, p, 2, 16);
    p += __shfl_down_sync(0xffffffffu, p, 1, 16);
    if ((tid & 15) == 0)
        g_scores[(tid >> 4) * SS + s] = any ? p * 0.125f : -INFINITY;  // 1/sqrt(64)
}

// -------- kernel C: partial softmax + A·V (flash-style, unnormalized) --------
// grid = 256 (h = b>>4, chunk = b&15), 256 threads. V read from ALIGNED oldc
// (shifted) with float4; only global row SS-1 comes from newc (scalar).
__global__ void __launch_bounds__(256) av_kernel(
    const float* __restrict__ oldc, const float* __restrict__ newc, int l) {
    __shared__ float red[32];
    __shared__ float p[256];
    __shared__ float4 pr4[16][16];
    int h = blockIdx.x >> 4, c = blockIdx.x & 15;
    int tid = threadIdx.x;
    float sc = g_scores[h * SS + (c << 8) + tid];
    float m = blockReduceMax(sc, red, 8);
    float e = (m == -INFINITY) ? 0.f : __expf(sc - m);
    float ssum = blockReduceSum(e, red, 8);
    p[tid] = e;
    __syncthreads();
    int d4 = tid & 15, sq = tid >> 4;
    size_t vbase = (size_t)(l * 2) * SS * D;
    const float4* ov4 = (const float4*)oldc + (vbase >> 2);
    int s0 = (c << 8) + (sq << 4);
    float4 acc = make_float4(0.f, 0.f, 0.f, 0.f);
    if (s0 + 15 < SS - 1) {
        const float4* vp = ov4 + (size_t)(s0 + 1) * 256 + (h << 4) + d4;
#pragma unroll
        for (int i = 0; i < 16; ++i) {
            float w = p[(sq << 4) + i];
            float4 vv = vp[(size_t)i * 256];
            acc.x += w * vv.x; acc.y += w * vv.y; acc.z += w * vv.z; acc.w += w * vv.w;
        }
    } else {
#pragma unroll
        for (int i = 0; i < 16; ++i) {
            int r = s0 + i;
            float w = p[(sq << 4) + i];
            float4 vv;
            if (r < SS - 1) {
                vv = ov4[(size_t)(r + 1) * 256 + (h << 4) + d4];
            } else {
                const float* nv = newc + vbase + (size_t)r * D + (h << 6) + (d4 << 2);
                vv = make_float4(nv[0], nv[1], nv[2], nv[3]);
            }
            acc.x += w * vv.x; acc.y += w * vv.y; acc.z += w * vv.z; acc.w += w * vv.w;
        }
    }
    pr4[sq][d4] = acc;
    __syncthreads();
    if (tid < 16) {
        float4 y = pr4[0][tid];
#pragma unroll
        for (int q = 1; q < 16; ++q) {
            float4 z = pr4[q][tid];
            y.x += z.x; y.y += z.y; y.z += z.z; y.w += z.w;
        }
        ((float4*)g_av_part)[(c << 8) + (h << 4) + tid] = y;
    }
    if (tid == 0) { g_m[(h << 4) + c] = m; g_s[(h << 4) + c] = ssum; }
}

// -------- kernels D/E/F: GEMV, grid = 32 blocks, 512 threads --------
// mode 0: flash-combine g_av_part -> vals; vals @ Wo + bo -> g_attnout
// mode 1: xmid = LN1(g_x + g_attnout); relu(xmid @ Wf1 + bf1) -> g_h1
// mode 2: g_h1 @ Wf2 + bf2 -> g_ffout
__global__ void __launch_bounds__(512) gemv_kernel(
    int mode, const float* __restrict__ W, const float* __restrict__ B,
    const float* __restrict__ ln_s, const float* __restrict__ ln_b) {
    __shared__ float xs[D];
    __shared__ float red[32];
    __shared__ float pr[8 * 64 * 4];
    __shared__ float hM[16], hS[16], wv[256];
    int tid = threadIdx.x;
    if (mode == 0) {
        if (tid < 16) {
            float M = -INFINITY;
#pragma unroll
            for (int c = 0; c < 16; ++c) M = fmaxf(M, g_m[(tid << 4) + c]);
            float S = 0.f;
#pragma unroll
            for (int c = 0; c < 16; ++c) {
                float mm = g_m[(tid << 4) + c];
                if (mm > -INFINITY) S += g_s[(tid << 4) + c] * __expf(mm - M);
            }
            hM[tid] = M; hS[tid] = 1.f / S;
        }
        __syncthreads();
        if (tid < 256) {
            int h = tid >> 4;
            float mm = g_m[tid];
            wv[tid] = (mm > -INFINITY) ? __expf(mm - hM[h]) * hS[h] : 0.f;
        }
        __syncthreads();
        if (tid < 256) {
            int h = tid >> 4;
            float4 acc = make_float4(0.f, 0.f, 0.f, 0.f);
#pragma unroll
            for (int c = 0; c < 16; ++c) {
                float4 p4 = ((const float4*)g_av_part)[(c << 8) + tid];
                float w = wv[(h << 4) + c];
                acc.x += w * p4.x; acc.y += w * p4.y; acc.z += w * p4.z; acc.w += w * p4.w;
            }
            ((float4*)xs)[tid] = acc;
        }
    } else if (mode == 1) {
        load_ln2(g_x, g_attnout, ln_s, ln_b, xs, red);
    } else {
        ((float2*)xs)[tid] = ((const float2*)g_h1)[tid];
    }
    __syncthreads();
    if (mode == 1 && blockIdx.x == 0) ((float2*)g_xmid)[tid] = ((float2*)xs)[tid];

    int jbase = blockIdx.x << 5;
    float v = gemv32_core(W, xs, jbase, pr);
    if (tid < 32) {
        int j = jbase + tid;
        float o = v + B[j];
        if (mode == 0)      g_attnout[j] = o;
        else if (mode == 1) g_h1[j] = fmaxf(o, 0.f);
        else                g_ffout[j] = o;
    }
}

// -------- final: LN2(last layer) -> x out, then 3 head GEMVs (47 outputs) --------
__global__ void __launch_bounds__(256) final_kernel(
    const float* __restrict__ ln2s, const float* __restrict__ ln2b,
    const float* __restrict__ Wpi, const float* __restrict__ bpi,
    const float* __restrict__ Wvh, const float* __restrict__ bvh,
    const float* __restrict__ Wc,  const float* __restrict__ bc,
    float* __restrict__ out) {
    __shared__ float xs[D];
    __shared__ float red[32];
    int tid = threadIdx.x;
    load_ln(g_xmid, g_ffout, ln2s, ln2b, xs, red);
    __syncthreads();
    ((float4*)out)[tid] = ((float4*)xs)[tid];
    int w = tid >> 5, lane = tid & 31;
    for (int j = w; j < NHEAD_OUT; j += 8) {
        const float* W; const float* BB; int col, N;
        if (j < 32)      { W = Wpi; BB = bpi; col = j;      N = 32; }
        else if (j < 39) { W = Wvh; BB = bvh; col = j - 32; N = 7;  }
        else             { W = Wc;  BB = bc;  col = j - 39; N = 8;  }
        float a = 0.f;
        for (int i = lane; i < D; i += 32) a += xs[i] * W[(size_t)i * N + col];
        a = warpReduceSum(a);
        if (lane == 0) out[D + j] = a + BB[col];
    }
}

extern "C" void kernel_launch(void* const* d_in, const int* in_sizes, int n_in,
                              void* d_out, int out_size) {
    const float* x    = (const float*)d_in[0];
    const float* cach = (const float*)d_in[1];
    const float* Wv   = (const float*)d_in[2];
    const float* bv   = (const float*)d_in[3];
    const float* Wq   = (const float*)d_in[4];
    const float* bq   = (const float*)d_in[5];
    const float* Wk   = (const float*)d_in[6];
    const float* bk   = (const float*)d_in[7];
    const float* Wo   = (const float*)d_in[8];
    const float* bo   = (const float*)d_in[9];
    const float* ln1s = (const float*)d_in[10];
    const float* ln1b = (const float*)d_in[11];
    const float* ln2s = (const float*)d_in[12];
    const float* ln2b = (const float*)d_in[13];
    const float* Wf1  = (const float*)d_in[14];
    const float* bf1  = (const float*)d_in[15];
    const float* Wf2  = (const float*)d_in[16];
    const float* bf2  = (const float*)d_in[17];
    const float* Wpi  = (const float*)d_in[18];
    const float* bpi  = (const float*)d_in[19];
    const float* Wvh  = (const float*)d_in[20];
    const float* bvh  = (const float*)d_in[21];
    const float* Wc   = (const float*)d_in[22];
    const float* bc   = (const float*)d_in[23];

    float* out  = (float*)d_out;
    float* newc = out + (D + NHEAD_OUT);  // cache region of flattened output tuple

    for (int l = 0; l < NL; ++l) {
        size_t mo = (size_t)l * D * D;
        size_t vo = (size_t)l * D;
        const float* p2s = (l > 0) ? (ln2s + (size_t)(l - 1) * D) : ln2s;
        const float* p2b = (l > 0) ? (ln2b + (size_t)(l - 1) * D) : ln2b;

        qkv_kernel<<<96, 512>>>(x, (l == 0) ? 1 : 0, p2s, p2b,
                                Wq + mo, Wk + mo, Wv + mo,
                                bq + vo, bk + vo, bv + vo, newc, l);
        scores_kernel<<<SS, 256>>>(cach, newc, l);
        av_kernel<<<256, 256>>>(cach, newc, l);
        gemv_kernel<<<32, 512>>>(0, Wo + mo, bo + vo, ln1s + vo, ln1b + vo);
        gemv_kernel<<<32, 512>>>(1, Wf1 + mo, bf1 + vo, ln1s + vo, ln1b + vo);
        gemv_kernel<<<32, 512>>>(2, Wf2 + mo, bf2 + vo, ln1s + vo, ln1b + vo);
    }
    final_kernel<<<1, 256>>>(ln2s + (size_t)(NL - 1) * D, ln2b + (size_t)(NL - 1) * D,
                             Wpi, bpi, Wvh, bvh, Wc, bc, out);
}

// round 6
// speedup vs baseline: 1.1958x; 1.1958x over previous
#include <cuda_runtime.h>
#include <math.h>

#define NL 24
#define D 1024
#define NH 16
#define SS 4096
#define HDIM 64
#define NHEAD_OUT 47   // 32 + 7 + 8

// -------- device scratch (allocation-free) --------
__device__ __align__(16) float g_q[D];
__device__ __align__(16) float g_x[D];        // layer input x (post prev LN2)
__device__ __align__(16) float g_xmid[D];     // LN1(x + attn_out)
__device__ __align__(16) float g_attnout[D];
__device__ __align__(16) float g_h1[D];
__device__ __align__(16) float g_ffout[D];
__device__ __align__(16) float g_scores[NH * SS];
__device__ __align__(16) float g_av_part[16 * D];  // [chunk][h*64+d] unnormalized
__device__ float g_m[NH * 16];   // per (head, chunk) max
__device__ float g_s[NH * 16];   // per (head, chunk) sum of exp

// -------- reductions --------
__device__ __forceinline__ float warpReduceSum(float v) {
#pragma unroll
    for (int o = 16; o > 0; o >>= 1) v += __shfl_down_sync(0xffffffffu, v, o);
    return v;
}
__device__ __forceinline__ float warpReduceMax(float v) {
#pragma unroll
    for (int o = 16; o > 0; o >>= 1) v = fmaxf(v, __shfl_down_sync(0xffffffffu, v, o));
    return v;
}
__device__ __forceinline__ float blockReduceSum(float v, float* red, int nw) {
    int tid = threadIdx.x;
    v = warpReduceSum(v);
    if ((tid & 31) == 0) red[tid >> 5] = v;
    __syncthreads();
    if (tid < 32) {
        float t = (tid < nw) ? red[tid] : 0.f;
        t = warpReduceSum(t);
        if (tid == 0) red[0] = t;
    }
    __syncthreads();
    float r = red[0];
    __syncthreads();
    return r;
}
__device__ __forceinline__ float blockReduceMax(float v, float* red, int nw) {
    int tid = threadIdx.x;
    v = warpReduceMax(v);
    if ((tid & 31) == 0) red[tid >> 5] = v;
    __syncthreads();
    if (tid < 32) {
        float t = (tid < nw) ? red[tid] : -INFINITY;
        t = warpReduceMax(t);
        if (tid == 0) red[0] = t;
    }
    __syncthreads();
    float r = red[0];
    __syncthreads();
    return r;
}

// LN(a+b)*sc+bi -> xs[D]; 256 threads, float4.
__device__ __forceinline__ void load_ln(const float* __restrict__ a, const float* __restrict__ b,
                                        const float* __restrict__ sc, const float* __restrict__ bi,
                                        float* xs, float* red) {
    int tid = threadIdx.x;
    float4 av = ((const float4*)a)[tid];
    float4 bv = ((const float4*)b)[tid];
    av.x += bv.x; av.y += bv.y; av.z += bv.z; av.w += bv.w;
    float sum = blockReduceSum(av.x + av.y + av.z + av.w, red, 8);
    float sq  = blockReduceSum(av.x*av.x + av.y*av.y + av.z*av.z + av.w*av.w, red, 8);
    float mean = sum * (1.f / D);
    float inv = rsqrtf(sq * (1.f / D) - mean * mean + 1e-6f);
    float4 s4 = ((const float4*)sc)[tid];
    float4 b4 = ((const float4*)bi)[tid];
    float4 o;
    o.x = (av.x - mean) * inv * s4.x + b4.x;
    o.y = (av.y - mean) * inv * s4.y + b4.y;
    o.z = (av.z - mean) * inv * s4.z + b4.z;
    o.w = (av.w - mean) * inv * s4.w + b4.w;
    ((float4*)xs)[tid] = o;
}

// GEMV core: 256 threads, 8 output cols per block (jbase..jbase+7).
// Thread (jq = tid&1, ks = tid>>1): cols jbase+4*jq.., rows 8*ks..8*ks+7.
// Front-batched 8x LDG.128, shuffle reduction. Returns col value on tid<8.
__device__ __forceinline__ float gemv8_core(const float* __restrict__ W, const float* xs,
                                            int jbase, float4* red4) {
    int tid = threadIdx.x;
    int jq = tid & 1, ks = tid >> 1;
    const float4* Wp = (const float4*)W + (size_t)(ks << 3) * 256 + (jbase >> 2) + jq;
    float4 w4[8];
#pragma unroll
    for (int i = 0; i < 8; ++i) w4[i] = Wp[(size_t)i * 256];
    float xr[8];
#pragma unroll
    for (int i = 0; i < 8; ++i) xr[i] = xs[(ks << 3) + i];
    float4 acc = make_float4(0.f, 0.f, 0.f, 0.f);
#pragma unroll
    for (int i = 0; i < 8; ++i) {
        acc.x += xr[i] * w4[i].x; acc.y += xr[i] * w4[i].y;
        acc.z += xr[i] * w4[i].z; acc.w += xr[i] * w4[i].w;
    }
    // shuffle-reduce over ks within warp (offsets 16,8,4,2 keep jq)
#pragma unroll
    for (int o = 16; o >= 2; o >>= 1) {
        acc.x += __shfl_down_sync(0xffffffffu, acc.x, o);
        acc.y += __shfl_down_sync(0xffffffffu, acc.y, o);
        acc.z += __shfl_down_sync(0xffffffffu, acc.z, o);
        acc.w += __shfl_down_sync(0xffffffffu, acc.w, o);
    }
    int lane = tid & 31, w = tid >> 5;
    if (lane < 2) red4[(w << 1) | lane] = acc;   // [warp][jq]
    __syncthreads();
    float v = 0.f;
    if (tid < 8) {
        int jqq = tid >> 2, comp = tid & 3;
#pragma unroll
        for (int ww = 0; ww < 8; ++ww) {
            float4 r = red4[(ww << 1) | jqq];
            v += (comp == 0) ? r.x : (comp == 1) ? r.y : (comp == 2) ? r.z : r.w;
        }
    }
    return v;
}

// -------- kernel A: (optional LN2 of prev layer) + q/k/v GEMVs --------
// grid = 384 (128 per matrix), 256 threads.
__global__ void __launch_bounds__(256) qkv_kernel(
    const float* __restrict__ xin, int first,
    const float* __restrict__ ln2s, const float* __restrict__ ln2b,
    const float* __restrict__ Wq, const float* __restrict__ Wk, const float* __restrict__ Wv,
    const float* __restrict__ bq, const float* __restrict__ bk, const float* __restrict__ bv,
    float* __restrict__ newc, int l) {
    __shared__ float xs[D];
    __shared__ float red[32];
    __shared__ float4 red4[16];
    int tid = threadIdx.x;
    if (first) {
        ((float4*)xs)[tid] = ((const float4*)xin)[tid];
    } else {
        load_ln(g_xmid, g_ffout, ln2s, ln2b, xs, red);
    }
    __syncthreads();
    if (blockIdx.x == 0) ((float4*)g_x)[tid] = ((float4*)xs)[tid];

    int m = blockIdx.x >> 7;                  // 0=q, 1=k, 2=v
    int jbase = (blockIdx.x & 127) << 3;
    const float* W = (m == 0) ? Wq : ((m == 1) ? Wk : Wv);
    const float* B = (m == 0) ? bq : ((m == 1) ? bk : bv);
    float v = gemv8_core(W, xs, jbase, red4);
    if (tid < 8) {
        int j = jbase + tid;
        float o = v + B[j];
        if (m == 0) g_q[j] = o;
        else {
            int plane = (m == 1) ? 1 : 0;     // plane0 = v, plane1 = k
            newc[((size_t)(l * 2 + plane) * SS + (SS - 1)) * D + j] = o;
        }
    }
}

// -------- kernel B: fused cache shift + mask + attention scores --------
// grid = 4096 (one block per seq pos), 256 threads.
__global__ void __launch_bounds__(256) scores_kernel(
    const float* __restrict__ oldc, float* __restrict__ newc, int l) {
    int s = blockIdx.x;
    int tid = threadIdx.x;
    size_t vbase = (size_t)(l * 2) * SS * D;
    size_t kbase = vbase + (size_t)SS * D;
    float4 v4, k4;
    if (s < SS - 1) {
        v4 = ((const float4*)(oldc + vbase + (size_t)(s + 1) * D))[tid];
        k4 = ((const float4*)(oldc + kbase + (size_t)(s + 1) * D))[tid];
        float* vd = newc + vbase + (size_t)s * D + (tid << 2);
        float* kd = newc + kbase + (size_t)s * D + (tid << 2);
        vd[0] = v4.x; vd[1] = v4.y; vd[2] = v4.z; vd[3] = v4.w;
        kd[0] = k4.x; kd[1] = k4.y; kd[2] = k4.z; kd[3] = k4.w;
    } else {
        const float* vs = newc + vbase + (size_t)s * D + (tid << 2);
        const float* kk = newc + kbase + (size_t)s * D + (tid << 2);
        v4 = make_float4(vs[0], vs[1], vs[2], vs[3]);
        k4 = make_float4(kk[0], kk[1], kk[2], kk[3]);
    }
    int nz = (v4.x != 0.f) || (v4.y != 0.f) || (v4.z != 0.f) || (v4.w != 0.f);
    int any = __syncthreads_or(nz);
    float4 q4 = ((const float4*)g_q)[tid];
    float p = q4.x * k4.x + q4.y * k4.y + q4.z * k4.z + q4.w * k4.w;
    p += __shfl_down_sync(0xffffffffu, p, 8, 16);
    p += __shfl_down_sync(0xffffffffu, p, 4, 16);
    p += __shfl_down_sync(0xffffffffu, p, 2, 16);
    p += __shfl_down_sync(0xffffffffu, p, 1, 16);
    if ((tid & 15) == 0)
        g_scores[(tid >> 4) * SS + s] = any ? p * 0.125f : -INFINITY;  // 1/sqrt(64)
}

// -------- kernel C: partial softmax + A·V (flash-style, unnormalized) --------
// grid = 256 (h = b>>4, chunk = b&15), 256 threads. V read from ALIGNED oldc.
__global__ void __launch_bounds__(256) av_kernel(
    const float* __restrict__ oldc, const float* __restrict__ newc, int l) {
    __shared__ float red[32];
    __shared__ float p[256];
    __shared__ float4 pr4[16][16];
    int h = blockIdx.x >> 4, c = blockIdx.x & 15;
    int tid = threadIdx.x;
    float sc = g_scores[h * SS + (c << 8) + tid];
    float m = blockReduceMax(sc, red, 8);
    float e = (m == -INFINITY) ? 0.f : __expf(sc - m);
    float ssum = blockReduceSum(e, red, 8);
    p[tid] = e;
    __syncthreads();
    int d4 = tid & 15, sq = tid >> 4;
    size_t vbase = (size_t)(l * 2) * SS * D;
    const float4* ov4 = (const float4*)oldc + (vbase >> 2);
    int s0 = (c << 8) + (sq << 4);
    float4 acc = make_float4(0.f, 0.f, 0.f, 0.f);
    if (s0 + 15 < SS - 1) {
        const float4* vp = ov4 + (size_t)(s0 + 1) * 256 + (h << 4) + d4;
#pragma unroll
        for (int i = 0; i < 16; ++i) {
            float w = p[(sq << 4) + i];
            float4 vv = vp[(size_t)i * 256];
            acc.x += w * vv.x; acc.y += w * vv.y; acc.z += w * vv.z; acc.w += w * vv.w;
        }
    } else {
#pragma unroll
        for (int i = 0; i < 16; ++i) {
            int r = s0 + i;
            float w = p[(sq << 4) + i];
            float4 vv;
            if (r < SS - 1) {
                vv = ov4[(size_t)(r + 1) * 256 + (h << 4) + d4];
            } else {
                const float* nv = newc + vbase + (size_t)r * D + (h << 6) + (d4 << 2);
                vv = make_float4(nv[0], nv[1], nv[2], nv[3]);
            }
            acc.x += w * vv.x; acc.y += w * vv.y; acc.z += w * vv.z; acc.w += w * vv.w;
        }
    }
    pr4[sq][d4] = acc;
    __syncthreads();
    if (tid < 16) {
        float4 y = pr4[0][tid];
#pragma unroll
        for (int q = 1; q < 16; ++q) {
            float4 z = pr4[q][tid];
            y.x += z.x; y.y += z.y; y.z += z.z; y.w += z.w;
        }
        ((float4*)g_av_part)[(c << 8) + (h << 4) + tid] = y;
    }
    if (tid == 0) { g_m[(h << 4) + c] = m; g_s[(h << 4) + c] = ssum; }
}

// -------- kernels D/E/F: GEMV, grid = 128 blocks, 256 threads --------
// mode 0: flash-combine g_av_part -> vals; vals @ Wo + bo -> g_attnout
// mode 1: xmid = LN1(g_x + g_attnout); relu(xmid @ Wf1 + bf1) -> g_h1
// mode 2: g_h1 @ Wf2 + bf2 -> g_ffout
__global__ void __launch_bounds__(256) gemv_kernel(
    int mode, const float* __restrict__ W, const float* __restrict__ B,
    const float* __restrict__ ln_s, const float* __restrict__ ln_b) {
    __shared__ float xs[D];
    __shared__ float red[32];
    __shared__ float4 red4[16];
    __shared__ float hM[16], hS[16], wv[256];
    int tid = threadIdx.x;
    if (mode == 0) {
        if (tid < 16) {
            float M = -INFINITY;
#pragma unroll
            for (int c = 0; c < 16; ++c) M = fmaxf(M, g_m[(tid << 4) + c]);
            float S = 0.f;
#pragma unroll
            for (int c = 0; c < 16; ++c) {
                float mm = g_m[(tid << 4) + c];
                if (mm > -INFINITY) S += g_s[(tid << 4) + c] * __expf(mm - M);
            }
            hM[tid] = M; hS[tid] = 1.f / S;
        }
        __syncthreads();
        {
            int h = tid >> 4;
            float mm = g_m[tid];
            wv[tid] = (mm > -INFINITY) ? __expf(mm - hM[h]) * hS[h] : 0.f;
        }
        __syncthreads();
        {
            int h = tid >> 4;
            float4 acc = make_float4(0.f, 0.f, 0.f, 0.f);
#pragma unroll
            for (int c = 0; c < 16; ++c) {
                float4 p4 = ((const float4*)g_av_part)[(c << 8) + tid];
                float w = wv[(h << 4) + c];
                acc.x += w * p4.x; acc.y += w * p4.y; acc.z += w * p4.z; acc.w += w * p4.w;
            }
            ((float4*)xs)[tid] = acc;
        }
    } else if (mode == 1) {
        load_ln(g_x, g_attnout, ln_s, ln_b, xs, red);
    } else {
        ((float4*)xs)[tid] = ((const float4*)g_h1)[tid];
    }
    __syncthreads();
    if (mode == 1 && blockIdx.x == 0) ((float4*)g_xmid)[tid] = ((float4*)xs)[tid];

    int jbase = blockIdx.x << 3;
    float v = gemv8_core(W, xs, jbase, red4);
    if (tid < 8) {
        int j = jbase + tid;
        float o = v + B[j];
        if (mode == 0)      g_attnout[j] = o;
        else if (mode == 1) g_h1[j] = fmaxf(o, 0.f);
        else                g_ffout[j] = o;
    }
}

// -------- final: LN2(last layer) -> x out, then 3 head GEMVs (47 outputs) --------
__global__ void __launch_bounds__(256) final_kernel(
    const float* __restrict__ ln2s, const float* __restrict__ ln2b,
    const float* __restrict__ Wpi, const float* __restrict__ bpi,
    const float* __restrict__ Wvh, const float* __restrict__ bvh,
    const float* __restrict__ Wc,  const float* __restrict__ bc,
    float* __restrict__ out) {
    __shared__ float xs[D];
    __shared__ float red[32];
    int tid = threadIdx.x;
    load_ln(g_xmid, g_ffout, ln2s, ln2b, xs, red);
    __syncthreads();
    ((float4*)out)[tid] = ((float4*)xs)[tid];
    int w = tid >> 5, lane = tid & 31;
    for (int j = w; j < NHEAD_OUT; j += 8) {
        const float* W; const float* BB; int col, N;
        if (j < 32)      { W = Wpi; BB = bpi; col = j;      N = 32; }
        else if (j < 39) { W = Wvh; BB = bvh; col = j - 32; N = 7;  }
        else             { W = Wc;  BB = bc;  col = j - 39; N = 8;  }
        float a = 0.f;
        for (int i = lane; i < D; i += 32) a += xs[i] * W[(size_t)i * N + col];
        a = warpReduceSum(a);
        if (lane == 0) out[D + j] = a + BB[col];
    }
}

extern "C" void kernel_launch(void* const* d_in, const int* in_sizes, int n_in,
                              void* d_out, int out_size) {
    const float* x    = (const float*)d_in[0];
    const float* cach = (const float*)d_in[1];
    const float* Wv   = (const float*)d_in[2];
    const float* bv   = (const float*)d_in[3];
    const float* Wq   = (const float*)d_in[4];
    const float* bq   = (const float*)d_in[5];
    const float* Wk   = (const float*)d_in[6];
    const float* bk   = (const float*)d_in[7];
    const float* Wo   = (const float*)d_in[8];
    const float* bo   = (const float*)d_in[9];
    const float* ln1s = (const float*)d_in[10];
    const float* ln1b = (const float*)d_in[11];
    const float* ln2s = (const float*)d_in[12];
    const float* ln2b = (const float*)d_in[13];
    const float* Wf1  = (const float*)d_in[14];
    const float* bf1  = (const float*)d_in[15];
    const float* Wf2  = (const float*)d_in[16];
    const float* bf2  = (const float*)d_in[17];
    const float* Wpi  = (const float*)d_in[18];
    const float* bpi  = (const float*)d_in[19];
    const float* Wvh  = (const float*)d_in[20];
    const float* bvh  = (const float*)d_in[21];
    const float* Wc   = (const float*)d_in[22];
    const float* bc   = (const float*)d_in[23];

    float* out  = (float*)d_out;
    float* newc = out + (D + NHEAD_OUT);  // cache region of flattened output tuple

    for (int l = 0; l < NL; ++l) {
        size_t mo = (size_t)l * D * D;
        size_t vo = (size_t)l * D;
        const float* p2s = (l > 0) ? (ln2s + (size_t)(l - 1) * D) : ln2s;
        const float* p2b = (l > 0) ? (ln2b + (size_t)(l - 1) * D) : ln2b;

        qkv_kernel<<<384, 256>>>(x, (l == 0) ? 1 : 0, p2s, p2b,
                                 Wq + mo, Wk + mo, Wv + mo,
                                 bq + vo, bk + vo, bv + vo, newc, l);
        scores_kernel<<<SS, 256>>>(cach, newc, l);
        av_kernel<<<256, 256>>>(cach, newc, l);
        gemv_kernel<<<128, 256>>>(0, Wo + mo, bo + vo, ln1s + vo, ln1b + vo);
        gemv_kernel<<<128, 256>>>(1, Wf1 + mo, bf1 + vo, ln1s + vo, ln1b + vo);
        gemv_kernel<<<128, 256>>>(2, Wf2 + mo, bf2 + vo, ln1s + vo, ln1b + vo);
    }
    final_kernel<<<1, 256>>>(ln2s + (size_t)(NL - 1) * D, ln2b + (size_t)(NL - 1) * D,
                             Wpi, bpi, Wvh, bvh, Wc, bc, out);
}

// round 7
// speedup vs baseline: 1.2069x; 1.0092x over previous
#include <cuda_runtime.h>
#include <math.h>

#define NL 24
#define D 1024
#define NH 16
#define SS 4096
#define HDIM 64
#define NHEAD_OUT 47   // 32 + 7 + 8

// -------- device scratch (allocation-free) --------
__device__ __align__(16) float g_q[D];
__device__ __align__(16) float g_x[D];        // layer input x (post prev LN2)
__device__ __align__(16) float g_xmid[D];     // LN1(x + attn_out)
__device__ __align__(16) float g_attnout[D];
__device__ __align__(16) float g_h1[D];
__device__ __align__(16) float g_ffout[D];
__device__ __align__(16) float g_scores[NH * SS];
__device__ __align__(16) float g_av_part[16 * D];  // [chunk][h*64+d] unnormalized
__device__ float g_m[NH * 16];   // per (head, chunk) max
__device__ float g_s[NH * 16];   // per (head, chunk) sum of exp

// -------- reductions --------
__device__ __forceinline__ float warpReduceSum(float v) {
#pragma unroll
    for (int o = 16; o > 0; o >>= 1) v += __shfl_down_sync(0xffffffffu, v, o);
    return v;
}
__device__ __forceinline__ float warpReduceMax(float v) {
#pragma unroll
    for (int o = 16; o > 0; o >>= 1) v = fmaxf(v, __shfl_down_sync(0xffffffffu, v, o));
    return v;
}
__device__ __forceinline__ float blockReduceSum(float v, float* red, int nw) {
    int tid = threadIdx.x;
    v = warpReduceSum(v);
    if ((tid & 31) == 0) red[tid >> 5] = v;
    __syncthreads();
    if (tid < 32) {
        float t = (tid < nw) ? red[tid] : 0.f;
        t = warpReduceSum(t);
        if (tid == 0) red[0] = t;
    }
    __syncthreads();
    float r = red[0];
    __syncthreads();
    return r;
}
__device__ __forceinline__ float blockReduceMax(float v, float* red, int nw) {
    int tid = threadIdx.x;
    v = warpReduceMax(v);
    if ((tid & 31) == 0) red[tid >> 5] = v;
    __syncthreads();
    if (tid < 32) {
        float t = (tid < nw) ? red[tid] : -INFINITY;
        t = warpReduceMax(t);
        if (tid == 0) red[0] = t;
    }
    __syncthreads();
    float r = red[0];
    __syncthreads();
    return r;
}

// LN(a+b)*sc+bi -> xs[D]; 256 threads, float4.
__device__ __forceinline__ void load_ln(const float* __restrict__ a, const float* __restrict__ b,
                                        const float* __restrict__ sc, const float* __restrict__ bi,
                                        float* xs, float* red) {
    int tid = threadIdx.x;
    float4 av = ((const float4*)a)[tid];
    float4 bv = ((const float4*)b)[tid];
    av.x += bv.x; av.y += bv.y; av.z += bv.z; av.w += bv.w;
    float sum = blockReduceSum(av.x + av.y + av.z + av.w, red, 8);
    float sq  = blockReduceSum(av.x*av.x + av.y*av.y + av.z*av.z + av.w*av.w, red, 8);
    float mean = sum * (1.f / D);
    float inv = rsqrtf(sq * (1.f / D) - mean * mean + 1e-6f);
    float4 s4 = ((const float4*)sc)[tid];
    float4 b4 = ((const float4*)bi)[tid];
    float4 o;
    o.x = (av.x - mean) * inv * s4.x + b4.x;
    o.y = (av.y - mean) * inv * s4.y + b4.y;
    o.z = (av.z - mean) * inv * s4.z + b4.z;
    o.w = (av.w - mean) * inv * s4.w + b4.w;
    ((float4*)xs)[tid] = o;
}

// LN(a+b)*sc+bi -> xs[D]; 512 threads, float2.
__device__ __forceinline__ void load_ln2(const float* __restrict__ a, const float* __restrict__ b,
                                         const float* __restrict__ sc, const float* __restrict__ bi,
                                         float* xs, float* red) {
    int tid = threadIdx.x;
    float2 av = ((const float2*)a)[tid];
    float2 bv = ((const float2*)b)[tid];
    av.x += bv.x; av.y += bv.y;
    float sum = blockReduceSum(av.x + av.y, red, 16);
    float sq  = blockReduceSum(av.x*av.x + av.y*av.y, red, 16);
    float mean = sum * (1.f / D);
    float inv = rsqrtf(sq * (1.f / D) - mean * mean + 1e-6f);
    float2 s2 = ((const float2*)sc)[tid];
    float2 b2 = ((const float2*)bi)[tid];
    float2 o;
    o.x = (av.x - mean) * inv * s2.x + b2.x;
    o.y = (av.y - mean) * inv * s2.y + b2.y;
    ((float2*)xs)[tid] = o;
}

// GEMV core, 512 threads: 8 output cols per block (jbase..jbase+7).
// Thread (jq = tid&1, rr = tid>>1): rows 4rr..4rr+3, float4-col (jbase>>2)+jq.
// Exactly 4 front-batched LDG.128 per thread (16 data regs), even-offset
// shuffle reduction (preserves jq), 16-warp smem combine.
// Returns col value on tid<8 (j = jbase + tid).
__device__ __forceinline__ float gemv512_core(const float* __restrict__ W, const float* xs,
                                              int jbase, float4* red4) {
    int tid = threadIdx.x;
    int jq = tid & 1, rr = tid >> 1;   // rr in 0..255
    const float4* Wp = (const float4*)W + (size_t)(rr << 2) * 256 + (jbase >> 2) + jq;
    float4 w0 = Wp[0];
    float4 w1 = Wp[256];
    float4 w2 = Wp[512];
    float4 w3 = Wp[768];
    float x0 = xs[(rr << 2) + 0];
    float x1 = xs[(rr << 2) + 1];
    float x2 = xs[(rr << 2) + 2];
    float x3 = xs[(rr << 2) + 3];
    float4 acc;
    acc.x = x0 * w0.x + x1 * w1.x + x2 * w2.x + x3 * w3.x;
    acc.y = x0 * w0.y + x1 * w1.y + x2 * w2.y + x3 * w3.y;
    acc.z = x0 * w0.z + x1 * w1.z + x2 * w2.z + x3 * w3.z;
    acc.w = x0 * w0.w + x1 * w1.w + x2 * w2.w + x3 * w3.w;
#pragma unroll
    for (int o = 16; o >= 2; o >>= 1) {   // even offsets keep jq parity
        acc.x += __shfl_down_sync(0xffffffffu, acc.x, o);
        acc.y += __shfl_down_sync(0xffffffffu, acc.y, o);
        acc.z += __shfl_down_sync(0xffffffffu, acc.z, o);
        acc.w += __shfl_down_sync(0xffffffffu, acc.w, o);
    }
    int lane = tid & 31, w = tid >> 5;    // 16 warps
    if (lane < 2) red4[(w << 1) | lane] = acc;  // [warp][jq]
    __syncthreads();
    float v = 0.f;
    if (tid < 8) {
        int jqq = tid >> 2, comp = tid & 3;
#pragma unroll
        for (int ww = 0; ww < 16; ++ww) {
            float4 r = red4[(ww << 1) | jqq];
            v += (comp == 0) ? r.x : (comp == 1) ? r.y : (comp == 2) ? r.z : r.w;
        }
    }
    return v;
}

// -------- kernel A: (optional LN2 of prev layer) + q/k/v GEMVs --------
// grid = 384 (128 per matrix), 512 threads.
__global__ void __launch_bounds__(512) qkv_kernel(
    const float* __restrict__ xin, int first,
    const float* __restrict__ ln2s, const float* __restrict__ ln2b,
    const float* __restrict__ Wq, const float* __restrict__ Wk, const float* __restrict__ Wv,
    const float* __restrict__ bq, const float* __restrict__ bk, const float* __restrict__ bv,
    float* __restrict__ newc, int l) {
    __shared__ float xs[D];
    __shared__ float red[32];
    __shared__ float4 red4[32];
    int tid = threadIdx.x;
    if (first) {
        ((float2*)xs)[tid] = ((const float2*)xin)[tid];
    } else {
        load_ln2(g_xmid, g_ffout, ln2s, ln2b, xs, red);
    }
    __syncthreads();
    if (blockIdx.x == 0) ((float2*)g_x)[tid] = ((float2*)xs)[tid];

    int m = blockIdx.x >> 7;                  // 0=q, 1=k, 2=v
    int jbase = (blockIdx.x & 127) << 3;
    const float* W = (m == 0) ? Wq : ((m == 1) ? Wk : Wv);
    const float* B = (m == 0) ? bq : ((m == 1) ? bk : bv);
    float v = gemv512_core(W, xs, jbase, red4);
    if (tid < 8) {
        int j = jbase + tid;
        float o = v + B[j];
        if (m == 0) g_q[j] = o;
        else {
            int plane = (m == 1) ? 1 : 0;     // plane0 = v, plane1 = k
            newc[((size_t)(l * 2 + plane) * SS + (SS - 1)) * D + j] = o;
        }
    }
}

// -------- kernel B: fused cache shift + mask + attention scores --------
// grid = 4096 (one block per seq pos), 256 threads.
__global__ void __launch_bounds__(256) scores_kernel(
    const float* __restrict__ oldc, float* __restrict__ newc, int l) {
    int s = blockIdx.x;
    int tid = threadIdx.x;
    size_t vbase = (size_t)(l * 2) * SS * D;
    size_t kbase = vbase + (size_t)SS * D;
    float4 v4, k4;
    if (s < SS - 1) {
        v4 = ((const float4*)(oldc + vbase + (size_t)(s + 1) * D))[tid];
        k4 = ((const float4*)(oldc + kbase + (size_t)(s + 1) * D))[tid];
        float* vd = newc + vbase + (size_t)s * D + (tid << 2);
        float* kd = newc + kbase + (size_t)s * D + (tid << 2);
        vd[0] = v4.x; vd[1] = v4.y; vd[2] = v4.z; vd[3] = v4.w;
        kd[0] = k4.x; kd[1] = k4.y; kd[2] = k4.z; kd[3] = k4.w;
    } else {
        const float* vs = newc + vbase + (size_t)s * D + (tid << 2);
        const float* kk = newc + kbase + (size_t)s * D + (tid << 2);
        v4 = make_float4(vs[0], vs[1], vs[2], vs[3]);
        k4 = make_float4(kk[0], kk[1], kk[2], kk[3]);
    }
    int nz = (v4.x != 0.f) || (v4.y != 0.f) || (v4.z != 0.f) || (v4.w != 0.f);
    int any = __syncthreads_or(nz);
    float4 q4 = ((const float4*)g_q)[tid];
    float p = q4.x * k4.x + q4.y * k4.y + q4.z * k4.z + q4.w * k4.w;
    p += __shfl_down_sync(0xffffffffu, p, 8, 16);
    p += __shfl_down_sync(0xffffffffu, p, 4, 16);
    p += __shfl_down_sync(0xffffffffu, p, 2, 16);
    p += __shfl_down_sync(0xffffffffu, p, 1, 16);
    if ((tid & 15) == 0)
        g_scores[(tid >> 4) * SS + s] = any ? p * 0.125f : -INFINITY;  // 1/sqrt(64)
}

// -------- kernel C: partial softmax + A·V (flash-style, unnormalized) --------
// grid = 256 (h = b>>4, chunk = b&15), 256 threads. V read from ALIGNED oldc.
__global__ void __launch_bounds__(256) av_kernel(
    const float* __restrict__ oldc, const float* __restrict__ newc, int l) {
    __shared__ float red[32];
    __shared__ float p[256];
    __shared__ float4 pr4[16][16];
    int h = blockIdx.x >> 4, c = blockIdx.x & 15;
    int tid = threadIdx.x;
    float sc = g_scores[h * SS + (c << 8) + tid];
    float m = blockReduceMax(sc, red, 8);
    float e = (m == -INFINITY) ? 0.f : __expf(sc - m);
    float ssum = blockReduceSum(e, red, 8);
    p[tid] = e;
    __syncthreads();
    int d4 = tid & 15, sq = tid >> 4;
    size_t vbase = (size_t)(l * 2) * SS * D;
    const float4* ov4 = (const float4*)oldc + (vbase >> 2);
    int s0 = (c << 8) + (sq << 4);
    float4 acc = make_float4(0.f, 0.f, 0.f, 0.f);
    if (s0 + 15 < SS - 1) {
        const float4* vp = ov4 + (size_t)(s0 + 1) * 256 + (h << 4) + d4;
#pragma unroll
        for (int i = 0; i < 16; ++i) {
            float w = p[(sq << 4) + i];
            float4 vv = vp[(size_t)i * 256];
            acc.x += w * vv.x; acc.y += w * vv.y; acc.z += w * vv.z; acc.w += w * vv.w;
        }
    } else {
#pragma unroll
        for (int i = 0; i < 16; ++i) {
            int r = s0 + i;
            float w = p[(sq << 4) + i];
            float4 vv;
            if (r < SS - 1) {
                vv = ov4[(size_t)(r + 1) * 256 + (h << 4) + d4];
            } else {
                const float* nv = newc + vbase + (size_t)r * D + (h << 6) + (d4 << 2);
                vv = make_float4(nv[0], nv[1], nv[2], nv[3]);
            }
            acc.x += w * vv.x; acc.y += w * vv.y; acc.z += w * vv.z; acc.w += w * vv.w;
        }
    }
    pr4[sq][d4] = acc;
    __syncthreads();
    if (tid < 16) {
        float4 y = pr4[0][tid];
#pragma unroll
        for (int q = 1; q < 16; ++q) {
            float4 z = pr4[q][tid];
            y.x += z.x; y.y += z.y; y.z += z.z; y.w += z.w;
        }
        ((float4*)g_av_part)[(c << 8) + (h << 4) + tid] = y;
    }
    if (tid == 0) { g_m[(h << 4) + c] = m; g_s[(h << 4) + c] = ssum; }
}

// -------- kernels D/E/F: GEMV, grid = 128 blocks, 512 threads --------
// mode 0: flash-combine g_av_part -> vals; vals @ Wo + bo -> g_attnout
// mode 1: xmid = LN1(g_x + g_attnout); relu(xmid @ Wf1 + bf1) -> g_h1
// mode 2: g_h1 @ Wf2 + bf2 -> g_ffout
__global__ void __launch_bounds__(512) gemv_kernel(
    int mode, const float* __restrict__ W, const float* __restrict__ B,
    const float* __restrict__ ln_s, const float* __restrict__ ln_b) {
    __shared__ float xs[D];
    __shared__ float red[32];
    __shared__ float4 red4[32];
    __shared__ float hM[16], hS[16], wv[256];
    int tid = threadIdx.x;
    if (mode == 0) {
        if (tid < 16) {
            float M = -INFINITY;
#pragma unroll
            for (int c = 0; c < 16; ++c) M = fmaxf(M, g_m[(tid << 4) + c]);
            float S = 0.f;
#pragma unroll
            for (int c = 0; c < 16; ++c) {
                float mm = g_m[(tid << 4) + c];
                if (mm > -INFINITY) S += g_s[(tid << 4) + c] * __expf(mm - M);
            }
            hM[tid] = M; hS[tid] = 1.f / S;
        }
        __syncthreads();
        if (tid < 256) {
            int h = tid >> 4;
            float mm = g_m[tid];
            wv[tid] = (mm > -INFINITY) ? __expf(mm - hM[h]) * hS[h] : 0.f;
        }
        __syncthreads();
        if (tid < 256) {
            int h = tid >> 4;
            float4 acc = make_float4(0.f, 0.f, 0.f, 0.f);
#pragma unroll
            for (int c = 0; c < 16; ++c) {
                float4 p4 = ((const float4*)g_av_part)[(c << 8) + tid];
                float w = wv[(h << 4) + c];
                acc.x += w * p4.x; acc.y += w * p4.y; acc.z += w * p4.z; acc.w += w * p4.w;
            }
            ((float4*)xs)[tid] = acc;
        }
    } else if (mode == 1) {
        load_ln2(g_x, g_attnout, ln_s, ln_b, xs, red);
    } else {
        ((float2*)xs)[tid] = ((const float2*)g_h1)[tid];
    }
    __syncthreads();
    if (mode == 1 && blockIdx.x == 0) ((float2*)g_xmid)[tid] = ((float2*)xs)[tid];

    int jbase = blockIdx.x << 3;
    float v = gemv512_core(W, xs, jbase, red4);
    if (tid < 8) {
        int j = jbase + tid;
        float o = v + B[j];
        if (mode == 0)      g_attnout[j] = o;
        else if (mode == 1) g_h1[j] = fmaxf(o, 0.f);
        else                g_ffout[j] = o;
    }
}

// -------- final: LN2(last layer) -> x out, then 3 head GEMVs (47 outputs) --------
__global__ void __launch_bounds__(256) final_kernel(
    const float* __restrict__ ln2s, const float* __restrict__ ln2b,
    const float* __restrict__ Wpi, const float* __restrict__ bpi,
    const float* __restrict__ Wvh, const float* __restrict__ bvh,
    const float* __restrict__ Wc,  const float* __restrict__ bc,
    float* __restrict__ out) {
    __shared__ float xs[D];
    __shared__ float red[32];
    int tid = threadIdx.x;
    load_ln(g_xmid, g_ffout, ln2s, ln2b, xs, red);
    __syncthreads();
    ((float4*)out)[tid] = ((float4*)xs)[tid];
    int w = tid >> 5, lane = tid & 31;
    for (int j = w; j < NHEAD_OUT; j += 8) {
        const float* W; const float* BB; int col, N;
        if (j < 32)      { W = Wpi; BB = bpi; col = j;      N = 32; }
        else if (j < 39) { W = Wvh; BB = bvh; col = j - 32; N = 7;  }
        else             { W = Wc;  BB = bc;  col = j - 39; N = 8;  }
        float a = 0.f;
        for (int i = lane; i < D; i += 32) a += xs[i] * W[(size_t)i * N + col];
        a = warpReduceSum(a);
        if (lane == 0) out[D + j] = a + BB[col];
    }
}

extern "C" void kernel_launch(void* const* d_in, const int* in_sizes, int n_in,
                              void* d_out, int out_size) {
    const float* x    = (const float*)d_in[0];
    const float* cach = (const float*)d_in[1];
    const float* Wv   = (const float*)d_in[2];
    const float* bv   = (const float*)d_in[3];
    const float* Wq   = (const float*)d_in[4];
    const float* bq   = (const float*)d_in[5];
    const float* Wk   = (const float*)d_in[6];
    const float* bk   = (const float*)d_in[7];
    const float* Wo   = (const float*)d_in[8];
    const float* bo   = (const float*)d_in[9];
    const float* ln1s = (const float*)d_in[10];
    const float* ln1b = (const float*)d_in[11];
    const float* ln2s = (const float*)d_in[12];
    const float* ln2b = (const float*)d_in[13];
    const float* Wf1  = (const float*)d_in[14];
    const float* bf1  = (const float*)d_in[15];
    const float* Wf2  = (const float*)d_in[16];
    const float* bf2  = (const float*)d_in[17];
    const float* Wpi  = (const float*)d_in[18];
    const float* bpi  = (const float*)d_in[19];
    const float* Wvh  = (const float*)d_in[20];
    const float* bvh  = (const float*)d_in[21];
    const float* Wc   = (const float*)d_in[22];
    const float* bc   = (const float*)d_in[23];

    float* out  = (float*)d_out;
    float* newc = out + (D + NHEAD_OUT);  // cache region of flattened output tuple

    for (int l = 0; l < NL; ++l) {
        size_t mo = (size_t)l * D * D;
        size_t vo = (size_t)l * D;
        const float* p2s = (l > 0) ? (ln2s + (size_t)(l - 1) * D) : ln2s;
        const float* p2b = (l > 0) ? (ln2b + (size_t)(l - 1) * D) : ln2b;

        qkv_kernel<<<384, 512>>>(x, (l == 0) ? 1 : 0, p2s, p2b,
                                 Wq + mo, Wk + mo, Wv + mo,
                                 bq + vo, bk + vo, bv + vo, newc, l);
        scores_kernel<<<SS, 256>>>(cach, newc, l);
        av_kernel<<<256, 256>>>(cach, newc, l);
        gemv_kernel<<<128, 512>>>(0, Wo + mo, bo + vo, ln1s + vo, ln1b + vo);
        gemv_kernel<<<128, 512>>>(1, Wf1 + mo, bf1 + vo, ln1s + vo, ln1b + vo);
        gemv_kernel<<<128, 512>>>(2, Wf2 + mo, bf2 + vo, ln1s + vo, ln1b + vo);
    }
    final_kernel<<<1, 256>>>(ln2s + (size_t)(NL - 1) * D, ln2b + (size_t)(NL - 1) * D,
                             Wpi, bpi, Wvh, bvh, Wc, bc, out);
}